// round 6
// baseline (speedup 1.0000x reference)
#include <cuda_runtime.h>
#include <cuda_fp16.h>
#include <cstdint>

#define EXPERTS 16
#define SEQ     2048
#define DIM     1024
#define HID     4096

// Scratch (no cudaMalloc allowed)
__device__ __half g_x16[(size_t)EXPERTS * SEQ * DIM];   // x    [e][n][d]
__device__ __half g_w1c[(size_t)EXPERTS * DIM * HID];   // w1   [e][d][h] (fp16 cast)
__device__ __half g_w2c[(size_t)EXPERTS * HID * DIM];   // w2   [e][h][d] (fp16 cast)
__device__ __half g_hid[(size_t)EXPERTS * SEQ * HID];   // gelu(x@w1) fp16

// ---------------- PTX helpers (base sm_103-safe only) ----------------
static __device__ __forceinline__ uint32_t smem_u32(const void* p) {
    return (uint32_t)__cvta_generic_to_shared(p);
}
static __device__ __forceinline__ void cp_async16(uint32_t s, const void* g) {
    asm volatile("cp.async.cg.shared.global [%0], [%1], 16;\n" :: "r"(s), "l"(g) : "memory");
}
static __device__ __forceinline__ void cp_commit() {
    asm volatile("cp.async.commit_group;\n" ::: "memory");
}
template <int N> static __device__ __forceinline__ void cp_wait() {
    asm volatile("cp.async.wait_group %0;\n" :: "n"(N) : "memory");
}
static __device__ __forceinline__ void ldsm_x4(uint32_t* r, uint32_t a) {
    asm volatile("ldmatrix.sync.aligned.m8n8.x4.shared.b16 {%0,%1,%2,%3}, [%4];"
                 : "=r"(r[0]), "=r"(r[1]), "=r"(r[2]), "=r"(r[3]) : "r"(a));
}
static __device__ __forceinline__ void ldsm_x4_t(uint32_t* r, uint32_t a) {
    asm volatile("ldmatrix.sync.aligned.m8n8.x4.trans.shared.b16 {%0,%1,%2,%3}, [%4];"
                 : "=r"(r[0]), "=r"(r[1]), "=r"(r[2]), "=r"(r[3]) : "r"(a));
}
static __device__ __forceinline__ void mma16816(float* d, const uint32_t* a,
                                                uint32_t b0, uint32_t b1) {
    asm volatile(
        "mma.sync.aligned.m16n8k16.row.col.f32.f16.f16.f32 "
        "{%0,%1,%2,%3}, {%4,%5,%6,%7}, {%8,%9}, {%0,%1,%2,%3};"
        : "+f"(d[0]), "+f"(d[1]), "+f"(d[2]), "+f"(d[3])
        : "r"(a[0]), "r"(a[1]), "r"(a[2]), "r"(a[3]), "r"(b0), "r"(b1));
}
static __device__ __forceinline__ float gelu_f(float v) {
    return 0.5f * v * (1.0f + erff(v * 0.70710678118654752f));
}

// ---------------- GEMM: C[BMxBN] = A[M,K](row) * B[K,N](row) ----------------
constexpr int BM = 128, BN = 256, BK = 64, STAGES = 3, NTHR = 512;
constexpr int A_ST = BM * BK * 2;                 // 16 KB (rows of 128B)
constexpr int B_ST = BK * BN * 2;                 // 32 KB (rows of 512B)
constexpr int SMEM_TOTAL = STAGES * (A_ST + B_ST);   // 147456 B

template <int GELU_OUT>
__global__ void __launch_bounds__(NTHR, 1)
gemm_mma(const __half* __restrict__ A0, const __half* __restrict__ B0,
         void* __restrict__ C0, int Kdim, int lda, int ldb, int ldc,
         size_t sA, size_t sB, size_t sC)
{
    extern __shared__ char smem[];
    const uint32_t sbase = smem_u32(smem);
    const int tid = threadIdx.x;
    const int e  = blockIdx.z;
    const int m0 = blockIdx.y * BM;
    const int n0 = blockIdx.x * BN;
    const __half* A = A0 + e * sA + (size_t)m0 * lda;
    const __half* B = B0 + e * sB;

    // cp.async slots. A: 1024 chunks (128 rows x 8); B: 2048 chunks (64 rows x 32).
    // Swizzle: 16B chunk index within each 128B block ^= (row & 7).
    uint32_t aOff[2]; const __half* aG[2];
#pragma unroll
    for (int j = 0; j < 2; j++) {
        int idx = tid + j * NTHR, r = idx >> 3, c = idx & 7;
        aOff[j] = (uint32_t)(r * 128 + ((c ^ (r & 7)) << 4));
        aG[j] = A + (size_t)r * lda + c * 8;
    }
    uint32_t bOff[4]; const __half* bG[4];
#pragma unroll
    for (int j = 0; j < 4; j++) {
        int idx = tid + j * NTHR, r = idx >> 5, cw = idx & 31;
        bOff[j] = (uint32_t)(r * 512 + ((cw >> 3) << 7) + (((cw & 7) ^ (r & 7)) << 4));
        bG[j] = B + (size_t)r * ldb + n0 + cw * 8;
    }

    // warp layout: 16 warps = 4(M) x 4(N); warp tile 32 x 64
    const int wid = tid >> 5, lid = tid & 31;
    const int wm = wid & 3, wn = wid >> 2;
    const int sub = lid >> 3, rr = lid & 7;
    const int rowA0 = wm * 32 + rr + ((sub & 1) << 3);    // + mt*16
    const int krow0 = rr + ((sub & 1) << 3);              // + kk*16
    const int nch0  = (wn * 64 + ((sub >> 1) << 3)) >> 3; // n 16B-chunk, + nt2*2

    float acc[2][8][4];
#pragma unroll
    for (int mt = 0; mt < 2; mt++)
#pragma unroll
        for (int nt = 0; nt < 8; nt++)
#pragma unroll
            for (int q = 0; q < 4; q++) acc[mt][nt][q] = 0.f;

    const int KITERS = Kdim / BK;

#pragma unroll
    for (int i = 0; i < STAGES - 1; i++) {        // prologue
        int k0 = i * BK;
#pragma unroll
        for (int j = 0; j < 2; j++) cp_async16(sbase + i * A_ST + aOff[j], aG[j] + k0);
#pragma unroll
        for (int j = 0; j < 4; j++)
            cp_async16(sbase + STAGES * A_ST + i * B_ST + bOff[j], bG[j] + (size_t)k0 * ldb);
        cp_commit();
    }

    for (int i = 0; i < KITERS; i++) {
        cp_wait<STAGES - 2>();
        __syncthreads();                          // stage i ready; slot (i-1)%S free

        int nx = i + STAGES - 1;
        if (nx < KITERS) {
            int s = nx % STAGES, k0 = nx * BK;
#pragma unroll
            for (int j = 0; j < 2; j++) cp_async16(sbase + s * A_ST + aOff[j], aG[j] + k0);
#pragma unroll
            for (int j = 0; j < 4; j++)
                cp_async16(sbase + STAGES * A_ST + s * B_ST + bOff[j], bG[j] + (size_t)k0 * ldb);
        }
        cp_commit();                              // commit even if empty: uniform counting

        const uint32_t sa  = sbase + (i % STAGES) * A_ST;
        const uint32_t sbb = sbase + STAGES * A_ST + (i % STAGES) * B_ST;
#pragma unroll
        for (int kk = 0; kk < 4; kk++) {
            uint32_t af[2][4];
#pragma unroll
            for (int mt = 0; mt < 2; mt++) {
                int row = rowA0 + mt * 16;
                int ch = 2 * kk + (sub >> 1);
                ldsm_x4(af[mt], sa + row * 128 + ((ch ^ (row & 7)) << 4));
            }
            uint32_t bf[4][4];
#pragma unroll
            for (int nt2 = 0; nt2 < 4; nt2++) {
                int krow = kk * 16 + krow0;
                int cw = nch0 + nt2 * 2;
                ldsm_x4_t(bf[nt2], sbb + krow * 512 + ((cw >> 3) << 7) +
                                   (((cw & 7) ^ (krow & 7)) << 4));
            }
#pragma unroll
            for (int mt = 0; mt < 2; mt++)
#pragma unroll
                for (int nt2 = 0; nt2 < 4; nt2++) {
                    mma16816(acc[mt][nt2 * 2],     af[mt], bf[nt2][0], bf[nt2][1]);
                    mma16816(acc[mt][nt2 * 2 + 1], af[mt], bf[nt2][2], bf[nt2][3]);
                }
        }
    }

    // Epilogue. C frag m16n8: lane -> row (lid>>2, +8), col (lid&3)*2.
    const int r0 = lid >> 2, cq = (lid & 3) * 2;
#pragma unroll
    for (int mt = 0; mt < 2; mt++) {
        int rbase = m0 + wm * 32 + mt * 16 + r0;
#pragma unroll
        for (int nt = 0; nt < 8; nt++) {
            int col = n0 + wn * 64 + nt * 8 + cq;
            float* q = acc[mt][nt];
            if (GELU_OUT) {
                __half* C = (__half*)C0 + e * sC + (size_t)rbase * ldc + col;
                __half2 h0 = __floats2half2_rn(gelu_f(q[0]), gelu_f(q[1]));
                __half2 h1 = __floats2half2_rn(gelu_f(q[2]), gelu_f(q[3]));
                *reinterpret_cast<__half2*>(C) = h0;
                *reinterpret_cast<__half2*>(C + (size_t)8 * ldc) = h1;
            } else {
                float* C = (float*)C0 + e * sC + (size_t)rbase * ldc + col;
                *reinterpret_cast<float2*>(C) = make_float2(q[0], q[1]);
                *reinterpret_cast<float2*>(C + (size_t)8 * ldc) = make_float2(q[2], q[3]);
            }
        }
    }
}

// ---------------- fp32 -> fp16 cast (no transpose needed) ----------------
__global__ void cvt_kernel(const float4* __restrict__ in, __half* __restrict__ out) {
    size_t i = (size_t)blockIdx.x * blockDim.x + threadIdx.x;  // exact grid
    float4 v = in[i];
    __half2 a = __floats2half2_rn(v.x, v.y);
    __half2 b = __floats2half2_rn(v.z, v.w);
    uint2 o;
    o.x = *reinterpret_cast<uint32_t*>(&a);
    o.y = *reinterpret_cast<uint32_t*>(&b);
    reinterpret_cast<uint2*>(out)[i] = o;
}

// ---------------- launch ----------------
extern "C" void kernel_launch(void* const* d_in, const int* in_sizes, int n_in,
                              void* d_out, int out_size) {
    const float* x  = (const float*)d_in[0];
    const float* w1 = (const float*)d_in[1];
    const float* w2 = (const float*)d_in[2];
    float* out = (float*)d_out;

    __half *px, *pw1, *pw2, *phid;
    cudaGetSymbolAddress((void**)&px,   g_x16);
    cudaGetSymbolAddress((void**)&pw1,  g_w1c);
    cudaGetSymbolAddress((void**)&pw2,  g_w2c);
    cudaGetSymbolAddress((void**)&phid, g_hid);

    cudaFuncSetAttribute(gemm_mma<1>, cudaFuncAttributeMaxDynamicSharedMemorySize, SMEM_TOTAL);
    cudaFuncSetAttribute(gemm_mma<0>, cudaFuncAttributeMaxDynamicSharedMemorySize, SMEM_TOTAL);

    const size_t nx = (size_t)EXPERTS * SEQ * DIM;   // 33.5M
    const size_t nw = (size_t)EXPERTS * DIM * HID;   // 67.1M
    cvt_kernel<<<(unsigned)(nx / 4 / 256), 256>>>((const float4*)x,  px);
    cvt_kernel<<<(unsigned)(nw / 4 / 256), 256>>>((const float4*)w1, pw1);
    cvt_kernel<<<(unsigned)(nw / 4 / 256), 256>>>((const float4*)w2, pw2);

    // GEMM1: hid = gelu(x @ w1)   M=SEQ, N=HID, K=DIM
    gemm_mma<1><<<dim3(HID / BN, SEQ / BM, EXPERTS), NTHR, SMEM_TOTAL>>>(
        px, pw1, phid, DIM, DIM, HID, HID,
        (size_t)SEQ * DIM, (size_t)DIM * HID, (size_t)SEQ * HID);

    // GEMM2: out = hid @ w2       M=SEQ, N=DIM, K=HID
    gemm_mma<0><<<dim3(DIM / BN, SEQ / BM, EXPERTS), NTHR, SMEM_TOTAL>>>(
        phid, pw2, out, HID, HID, DIM, DIM,
        (size_t)SEQ * HID, (size_t)HID * DIM, (size_t)SEQ * DIM);
}

// round 7
// speedup vs baseline: 1.0581x; 1.0581x over previous
#include <cuda_runtime.h>
#include <cuda_fp16.h>
#include <cstdint>

#define EXPERTS 16
#define SEQ     2048
#define DIM     1024
#define HID     4096

// Scratch (no cudaMalloc allowed)
__device__ __half g_x16[(size_t)EXPERTS * SEQ * DIM];   // x    [e][n][d]
__device__ __half g_w1c[(size_t)EXPERTS * DIM * HID];   // w1   [e][d][h] (fp16 cast)
__device__ __half g_w2c[(size_t)EXPERTS * HID * DIM];   // w2   [e][h][d] (fp16 cast)
__device__ __half g_hid[(size_t)EXPERTS * SEQ * HID];   // gelu(x@w1) fp16

// ---------------- PTX helpers (base sm_103-safe only) ----------------
static __device__ __forceinline__ uint32_t smem_u32(const void* p) {
    return (uint32_t)__cvta_generic_to_shared(p);
}
static __device__ __forceinline__ void cp_async16(uint32_t s, const void* g) {
    asm volatile("cp.async.cg.shared.global [%0], [%1], 16;\n" :: "r"(s), "l"(g) : "memory");
}
static __device__ __forceinline__ void cp_commit() {
    asm volatile("cp.async.commit_group;\n" ::: "memory");
}
template <int N> static __device__ __forceinline__ void cp_wait() {
    asm volatile("cp.async.wait_group %0;\n" :: "n"(N) : "memory");
}
static __device__ __forceinline__ void ldsm_x4(uint32_t* r, uint32_t a) {
    asm volatile("ldmatrix.sync.aligned.m8n8.x4.shared.b16 {%0,%1,%2,%3}, [%4];"
                 : "=r"(r[0]), "=r"(r[1]), "=r"(r[2]), "=r"(r[3]) : "r"(a));
}
static __device__ __forceinline__ void ldsm_x4_t(uint32_t* r, uint32_t a) {
    asm volatile("ldmatrix.sync.aligned.m8n8.x4.trans.shared.b16 {%0,%1,%2,%3}, [%4];"
                 : "=r"(r[0]), "=r"(r[1]), "=r"(r[2]), "=r"(r[3]) : "r"(a));
}
static __device__ __forceinline__ void mma16816(float* d, const uint32_t* a,
                                                uint32_t b0, uint32_t b1) {
    asm volatile(
        "mma.sync.aligned.m16n8k16.row.col.f32.f16.f16.f32 "
        "{%0,%1,%2,%3}, {%4,%5,%6,%7}, {%8,%9}, {%0,%1,%2,%3};"
        : "+f"(d[0]), "+f"(d[1]), "+f"(d[2]), "+f"(d[3])
        : "r"(a[0]), "r"(a[1]), "r"(a[2]), "r"(a[3]), "r"(b0), "r"(b1));
}
static __device__ __forceinline__ float gelu_f(float v) {
    return 0.5f * v * (1.0f + erff(v * 0.70710678118654752f));
}

// -------- GEMM: C[BMxBN] = A[M,K](row) * B[K,N](row); 2 CTAs/SM --------
constexpr int BM = 128, BN = 128, BK = 64, STAGES = 3, NTHR = 256;
constexpr int A_ST = BM * BK * 2;                    // 16 KB (rows of 128B)
constexpr int B_ST = BK * BN * 2;                    // 16 KB (rows of 256B)
constexpr int SMEM_TOTAL = STAGES * (A_ST + B_ST);   // 98304 B -> 2 CTA/SM

template <int GELU_OUT>
__global__ void __launch_bounds__(NTHR, 2)
gemm_mma(const __half* __restrict__ A0, const __half* __restrict__ B0,
         void* __restrict__ C0, int Kdim, int lda, int ldb, int ldc,
         size_t sA, size_t sB, size_t sC)
{
    extern __shared__ char smem[];
    const uint32_t sbase = smem_u32(smem);
    const int tid = threadIdx.x;
    const int e  = blockIdx.z;
    const int m0 = blockIdx.y * BM;
    const int n0 = blockIdx.x * BN;
    const __half* A = A0 + e * sA + (size_t)m0 * lda;
    const __half* B = B0 + e * sB;

    // cp.async slots. A: 1024 16B chunks (128 rows x 8); B: 1024 (64 rows x 16).
    // Swizzle: chunk index within each 128B block ^= (row & 7).
    uint32_t aOff[4]; const __half* aG[4];
#pragma unroll
    for (int j = 0; j < 4; j++) {
        int idx = tid + j * NTHR, r = idx >> 3, c = idx & 7;
        aOff[j] = (uint32_t)(r * 128 + ((c ^ (r & 7)) << 4));
        aG[j] = A + (size_t)r * lda + c * 8;
    }
    uint32_t bOff[4]; const __half* bG[4];
#pragma unroll
    for (int j = 0; j < 4; j++) {
        int idx = tid + j * NTHR, r = idx >> 4, cw = idx & 15;
        bOff[j] = (uint32_t)(r * 256 + ((cw >> 3) << 7) + (((cw & 7) ^ (r & 7)) << 4));
        bG[j] = B + (size_t)r * ldb + n0 + cw * 8;
    }

    // 8 warps = 4(M) x 2(N); warp tile 32 x 64
    const int wid = tid >> 5, lid = tid & 31;
    const int wm = wid & 3, wn = wid >> 2;
    const int sub = lid >> 3, rr = lid & 7;
    const int rowA0 = wm * 32 + rr + ((sub & 1) << 3);    // + mt*16
    const int krow0 = rr + ((sub & 1) << 3);              // + kk*16
    const int nch0  = (wn * 64 + ((sub >> 1) << 3)) >> 3; // 16B-chunk (of 16/row), + nt2*2

    float acc[2][8][4];
#pragma unroll
    for (int mt = 0; mt < 2; mt++)
#pragma unroll
        for (int nt = 0; nt < 8; nt++)
#pragma unroll
            for (int q = 0; q < 4; q++) acc[mt][nt][q] = 0.f;

    const int KITERS = Kdim / BK;

#pragma unroll
    for (int i = 0; i < STAGES - 1; i++) {        // prologue
        int k0 = i * BK;
#pragma unroll
        for (int j = 0; j < 4; j++) cp_async16(sbase + i * A_ST + aOff[j], aG[j] + k0);
#pragma unroll
        for (int j = 0; j < 4; j++)
            cp_async16(sbase + STAGES * A_ST + i * B_ST + bOff[j], bG[j] + (size_t)k0 * ldb);
        cp_commit();
    }

    for (int i = 0; i < KITERS; i++) {
        cp_wait<STAGES - 2>();
        __syncthreads();                          // stage i ready

        int nx = i + STAGES - 1;
        if (nx < KITERS) {
            int s = nx % STAGES, k0 = nx * BK;
#pragma unroll
            for (int j = 0; j < 4; j++) cp_async16(sbase + s * A_ST + aOff[j], aG[j] + k0);
#pragma unroll
            for (int j = 0; j < 4; j++)
                cp_async16(sbase + STAGES * A_ST + s * B_ST + bOff[j], bG[j] + (size_t)k0 * ldb);
        }
        cp_commit();                              // uniform group counting

        const uint32_t sa  = sbase + (i % STAGES) * A_ST;
        const uint32_t sbb = sbase + STAGES * A_ST + (i % STAGES) * B_ST;
#pragma unroll
        for (int kk = 0; kk < 4; kk++) {
            uint32_t af[2][4];
#pragma unroll
            for (int mt = 0; mt < 2; mt++) {
                int row = rowA0 + mt * 16;
                int ch = 2 * kk + (sub >> 1);
                ldsm_x4(af[mt], sa + row * 128 + ((ch ^ (row & 7)) << 4));
            }
            uint32_t bf[4][4];
#pragma unroll
            for (int nt2 = 0; nt2 < 4; nt2++) {
                int krow = kk * 16 + krow0;
                int cw = nch0 + nt2 * 2;
                ldsm_x4_t(bf[nt2], sbb + krow * 256 + ((cw >> 3) << 7) +
                                   (((cw & 7) ^ (krow & 7)) << 4));
            }
#pragma unroll
            for (int mt = 0; mt < 2; mt++)
#pragma unroll
                for (int nt2 = 0; nt2 < 4; nt2++) {
                    mma16816(acc[mt][nt2 * 2],     af[mt], bf[nt2][0], bf[nt2][1]);
                    mma16816(acc[mt][nt2 * 2 + 1], af[mt], bf[nt2][2], bf[nt2][3]);
                }
        }
    }

    // Epilogue. C frag m16n8: lane -> row (lid>>2, +8), col (lid&3)*2.
    const int r0 = lid >> 2, cq = (lid & 3) * 2;
#pragma unroll
    for (int mt = 0; mt < 2; mt++) {
        int rbase = m0 + wm * 32 + mt * 16 + r0;
#pragma unroll
        for (int nt = 0; nt < 8; nt++) {
            int col = n0 + wn * 64 + nt * 8 + cq;
            float* q = acc[mt][nt];
            if (GELU_OUT) {
                __half* C = (__half*)C0 + e * sC + (size_t)rbase * ldc + col;
                __half2 h0 = __floats2half2_rn(gelu_f(q[0]), gelu_f(q[1]));
                __half2 h1 = __floats2half2_rn(gelu_f(q[2]), gelu_f(q[3]));
                *reinterpret_cast<__half2*>(C) = h0;
                *reinterpret_cast<__half2*>(C + (size_t)8 * ldc) = h1;
            } else {
                float* C = (float*)C0 + e * sC + (size_t)rbase * ldc + col;
                *reinterpret_cast<float2*>(C) = make_float2(q[0], q[1]);
                *reinterpret_cast<float2*>(C + (size_t)8 * ldc) = make_float2(q[2], q[3]);
            }
        }
    }
}

// ---------------- fp32 -> fp16 cast ----------------
__global__ void cvt_kernel(const float4* __restrict__ in, __half* __restrict__ out) {
    size_t i = (size_t)blockIdx.x * blockDim.x + threadIdx.x;  // exact grid
    float4 v = in[i];
    __half2 a = __floats2half2_rn(v.x, v.y);
    __half2 b = __floats2half2_rn(v.z, v.w);
    uint2 o;
    o.x = *reinterpret_cast<uint32_t*>(&a);
    o.y = *reinterpret_cast<uint32_t*>(&b);
    reinterpret_cast<uint2*>(out)[i] = o;
}

// ---------------- launch ----------------
extern "C" void kernel_launch(void* const* d_in, const int* in_sizes, int n_in,
                              void* d_out, int out_size) {
    const float* x  = (const float*)d_in[0];
    const float* w1 = (const float*)d_in[1];
    const float* w2 = (const float*)d_in[2];
    float* out = (float*)d_out;

    __half *px, *pw1, *pw2, *phid;
    cudaGetSymbolAddress((void**)&px,   g_x16);
    cudaGetSymbolAddress((void**)&pw1,  g_w1c);
    cudaGetSymbolAddress((void**)&pw2,  g_w2c);
    cudaGetSymbolAddress((void**)&phid, g_hid);

    cudaFuncSetAttribute(gemm_mma<1>, cudaFuncAttributeMaxDynamicSharedMemorySize, SMEM_TOTAL);
    cudaFuncSetAttribute(gemm_mma<0>, cudaFuncAttributeMaxDynamicSharedMemorySize, SMEM_TOTAL);

    const size_t nx = (size_t)EXPERTS * SEQ * DIM;   // 33.5M
    const size_t nw = (size_t)EXPERTS * DIM * HID;   // 67.1M
    cvt_kernel<<<(unsigned)(nx / 4 / 256), 256>>>((const float4*)x,  px);
    cvt_kernel<<<(unsigned)(nw / 4 / 256), 256>>>((const float4*)w1, pw1);
    cvt_kernel<<<(unsigned)(nw / 4 / 256), 256>>>((const float4*)w2, pw2);

    // GEMM1: hid = gelu(x @ w1)   M=SEQ, N=HID, K=DIM
    gemm_mma<1><<<dim3(HID / BN, SEQ / BM, EXPERTS), NTHR, SMEM_TOTAL>>>(
        px, pw1, phid, DIM, DIM, HID, HID,
        (size_t)SEQ * DIM, (size_t)DIM * HID, (size_t)SEQ * HID);

    // GEMM2: out = hid @ w2       M=SEQ, N=DIM, K=HID
    gemm_mma<0><<<dim3(DIM / BN, SEQ / BM, EXPERTS), NTHR, SMEM_TOTAL>>>(
        phid, pw2, out, HID, HID, DIM, DIM,
        (size_t)SEQ * HID, (size_t)HID * DIM, (size_t)SEQ * DIM);
}

// round 8
// speedup vs baseline: 1.1045x; 1.0438x over previous
#include <cuda_runtime.h>
#include <cuda_fp16.h>
#include <cstdint>

#define EXPERTS 16
#define SEQ     2048
#define DIM     1024
#define HID     4096

// Tiled+swizzled fp16 scratch. A-tile = 128x64 (16KB), B-tile = 64x128 (16KB),
// stored exactly in the smem image so the mainloop does contiguous 16KB bulk copies.
__device__ __half g_xT [(size_t)EXPERTS * SEQ * DIM];   // x   A-tiles [e][mt][kt]
__device__ __half g_w1T[(size_t)EXPERTS * DIM * HID];   // w1  B-tiles [e][kt][nt]
__device__ __half g_w2T[(size_t)EXPERTS * HID * DIM];   // w2  B-tiles [e][kt][nt]
__device__ __half g_hT [(size_t)EXPERTS * SEQ * HID];   // gelu(x@w1) A-tiles [e][mt][kt]

// ---------------- PTX helpers (base sm_103-safe) ----------------
static __device__ __forceinline__ uint32_t smem_u32(const void* p) {
    return (uint32_t)__cvta_generic_to_shared(p);
}
static __device__ __forceinline__ void mbar_init(uint32_t a, uint32_t cnt) {
    asm volatile("mbarrier.init.shared.b64 [%0], %1;" :: "r"(a), "r"(cnt) : "memory");
}
static __device__ __forceinline__ void mbar_expect(uint32_t a, uint32_t bytes) {
    asm volatile("mbarrier.arrive.expect_tx.shared.b64 _, [%0], %1;"
                 :: "r"(a), "r"(bytes) : "memory");
}
static __device__ __forceinline__ void bulk_g2s(uint32_t dst, const void* src,
                                                uint32_t bytes, uint32_t mbar) {
    asm volatile(
        "cp.async.bulk.shared::cluster.global.mbarrier::complete_tx::bytes "
        "[%0], [%1], %2, [%3];"
        :: "r"(dst), "l"(src), "r"(bytes), "r"(mbar) : "memory");
}
static __device__ __forceinline__ void mbar_wait(uint32_t a, uint32_t parity) {
    asm volatile(
        "{\n\t.reg .pred P;\n\t"
        "WL%=:\n\t"
        "mbarrier.try_wait.parity.acquire.cta.shared::cta.b64 P, [%0], %1, 0x989680;\n\t"
        "@!P bra WL%=;\n\t}"
        :: "r"(a), "r"(parity) : "memory");
}
static __device__ __forceinline__ void ldsm_x4(uint32_t* r, uint32_t a) {
    asm volatile("ldmatrix.sync.aligned.m8n8.x4.shared.b16 {%0,%1,%2,%3}, [%4];"
                 : "=r"(r[0]), "=r"(r[1]), "=r"(r[2]), "=r"(r[3]) : "r"(a));
}
static __device__ __forceinline__ void ldsm_x4_t(uint32_t* r, uint32_t a) {
    asm volatile("ldmatrix.sync.aligned.m8n8.x4.trans.shared.b16 {%0,%1,%2,%3}, [%4];"
                 : "=r"(r[0]), "=r"(r[1]), "=r"(r[2]), "=r"(r[3]) : "r"(a));
}
static __device__ __forceinline__ void mma16816(float* d, const uint32_t* a,
                                                uint32_t b0, uint32_t b1) {
    asm volatile(
        "mma.sync.aligned.m16n8k16.row.col.f32.f16.f16.f32 "
        "{%0,%1,%2,%3}, {%4,%5,%6,%7}, {%8,%9}, {%0,%1,%2,%3};"
        : "+f"(d[0]), "+f"(d[1]), "+f"(d[2]), "+f"(d[3])
        : "r"(a[0]), "r"(a[1]), "r"(a[2]), "r"(a[3]), "r"(b0), "r"(b1));
}
static __device__ __forceinline__ float gelu_f(float v) {
    return 0.5f * v * (1.0f + erff(v * 0.70710678118654752f));
}

// -------- GEMM: C[128x128] = A-tiles x B-tiles; 2 CTAs/SM --------
constexpr int BM = 128, BN = 128, BK = 64, STAGES = 3, NTHR = 256;
constexpr int TILE_B = 16384;                        // bytes per tile
constexpr int ST_B   = 2 * TILE_B;                   // A+B per stage
constexpr int OFF_T  = 1024;                         // barriers below
constexpr int SMEM_TOTAL = OFF_T + STAGES * ST_B;    // 99328 -> 2 CTA/SM

// GELU_OUT=1: C = g_hT as A-tiles for GEMM2 (KT2=HID/64=64, MT=16), fp16+gelu
// GELU_OUT=0: C = row-major fp32 (ldc, sC)
template <int GELU_OUT>
__global__ void __launch_bounds__(NTHR, 2)
gemm_bulk(const __half* __restrict__ Atiles, const __half* __restrict__ Btiles,
          void* __restrict__ C0, int KT, int NT, int ldc, size_t sC)
{
    extern __shared__ char smem[];
    const uint32_t sb = smem_u32(smem);
    const int tid = threadIdx.x;
    const int e = blockIdx.z, by = blockIdx.y, bx = blockIdx.x;

    const char* Abase = (const char*)Atiles + ((size_t)(e * gridDim.y + by) * KT) * TILE_B;
    const char* Bbase = (const char*)Btiles + ((size_t)e * KT * NT + bx) * TILE_B;
    const size_t bstep = (size_t)NT * TILE_B;

    if (tid == 0) {
#pragma unroll
        for (int s = 0; s < STAGES; s++) mbar_init(sb + 8 * s, 1);
    }
    __syncthreads();

    const int wid = tid >> 5, lid = tid & 31;
    const int wm = wid & 3, wn = wid >> 2;            // 4(M) x 2(N), warp tile 32x64
    const int sub = lid >> 3, rr = lid & 7;
    const int rowA0 = wm * 32 + rr + ((sub & 1) << 3);
    const int krow0 = rr + ((sub & 1) << 3);
    const int nch0  = (wn * 64 + ((sub >> 1) << 3)) >> 3;

    float acc[2][8][4];
#pragma unroll
    for (int mt = 0; mt < 2; mt++)
#pragma unroll
        for (int nt = 0; nt < 8; nt++)
#pragma unroll
            for (int q = 0; q < 4; q++) acc[mt][nt][q] = 0.f;

    const int KITERS = KT;

    // producer: one thread, two 16KB bulk copies per stage
    if (tid == 0) {
#pragma unroll
        for (int it = 0; it < STAGES - 1; it++) {
            uint32_t mb = sb + 8 * it, da = sb + OFF_T + it * ST_B;
            mbar_expect(mb, ST_B);
            bulk_g2s(da,          Abase + (size_t)it * TILE_B, TILE_B, mb);
            bulk_g2s(da + TILE_B, Bbase + (size_t)it * bstep,  TILE_B, mb);
        }
    }

    for (int i = 0; i < KITERS; i++) {
        const int s = i % STAGES;
        mbar_wait(sb + 8 * s, (i / STAGES) & 1);

        const uint32_t sa  = sb + OFF_T + s * ST_B;
        const uint32_t sbb = sa + TILE_B;
#pragma unroll
        for (int kk = 0; kk < 4; kk++) {
            uint32_t af[2][4];
#pragma unroll
            for (int mt = 0; mt < 2; mt++) {
                int row = rowA0 + mt * 16;
                int ch = 2 * kk + (sub >> 1);
                ldsm_x4(af[mt], sa + row * 128 + ((ch ^ (row & 7)) << 4));
            }
            uint32_t bf[4][4];
#pragma unroll
            for (int nt2 = 0; nt2 < 4; nt2++) {
                int krow = kk * 16 + krow0;
                int cw = nch0 + nt2 * 2;
                ldsm_x4_t(bf[nt2], sbb + krow * 256 + ((cw >> 3) << 7) +
                                   (((cw & 7) ^ (krow & 7)) << 4));
            }
#pragma unroll
            for (int mt = 0; mt < 2; mt++)
#pragma unroll
                for (int nt2 = 0; nt2 < 4; nt2++) {
                    mma16816(acc[mt][nt2 * 2],     af[mt], bf[nt2][0], bf[nt2][1]);
                    mma16816(acc[mt][nt2 * 2 + 1], af[mt], bf[nt2][2], bf[nt2][3]);
                }
        }
        __syncthreads();                     // everyone done with slot s
        int nx = i + STAGES - 1;
        if (tid == 0 && nx < KITERS) {       // refill slot (i-1)%STAGES
            int s2 = nx % STAGES;
            uint32_t mb = sb + 8 * s2, da = sb + OFF_T + s2 * ST_B;
            mbar_expect(mb, ST_B);
            bulk_g2s(da,          Abase + (size_t)nx * TILE_B, TILE_B, mb);
            bulk_g2s(da + TILE_B, Bbase + (size_t)nx * bstep,  TILE_B, mb);
        }
    }

    // Epilogue. C frag m16n8: lane -> rows r0, r0+8 ; cols cq, cq+1.
    const int r0 = lid >> 2, cq = (lid & 3) * 2;
    if (GELU_OUT) {
        // write g_hT as GEMM2 A-tiles: tile (e, mt=by, ktg = bx*2 + (cl>>6))
        char* Hb = (char*)C0 + ((size_t)(e * (SEQ / 128) + by) * (HID / 64) + bx * 2) * TILE_B;
#pragma unroll
        for (int mt = 0; mt < 2; mt++) {
            int r1 = wm * 32 + mt * 16 + r0;          // r1&7 == r0
#pragma unroll
            for (int nt = 0; nt < 8; nt++) {
                int cl = wn * 64 + nt * 8 + cq;
                int cc = cl & 63;
                float* q = acc[mt][nt];
                __half2 h0 = __floats2half2_rn(gelu_f(q[0]), gelu_f(q[1]));
                __half2 h1 = __floats2half2_rn(gelu_f(q[2]), gelu_f(q[3]));
                char* p = Hb + ((size_t)(cl >> 6) << 14)
                             + ((((cc >> 3) ^ (r0 & 7)) << 4) + (cc & 7) * 2);
                *reinterpret_cast<__half2*>(p + (size_t)r1 * 128) = h0;
                *reinterpret_cast<__half2*>(p + (size_t)(r1 + 8) * 128) = h1;
            }
        }
    } else {
        const int m0 = by * BM, n0 = bx * BN;
#pragma unroll
        for (int mt = 0; mt < 2; mt++) {
            int rbase = m0 + wm * 32 + mt * 16 + r0;
#pragma unroll
            for (int nt = 0; nt < 8; nt++) {
                int col = n0 + wn * 64 + nt * 8 + cq;
                float* q = acc[mt][nt];
                float* C = (float*)C0 + e * sC + (size_t)rbase * ldc + col;
                *reinterpret_cast<float2*>(C) = make_float2(q[0], q[1]);
                *reinterpret_cast<float2*>(C + (size_t)8 * ldc) = make_float2(q[2], q[3]);
            }
        }
    }
}

// ---------------- conversion: fp32 -> fp16 tiled+swizzled ----------------
// x [e][n][d] -> A-tiles [e][mt][kt][128x64 swizzled]
__global__ void cvt_x_tiled(const float4* __restrict__ in) {
    size_t i = (size_t)blockIdx.x * blockDim.x + threadIdx.x;  // E*SEQ*DIM/4
    size_t base = i * 4;
    int d = (int)(base % DIM);
    size_t nd = base / DIM;
    int n = (int)(nd % SEQ);
    int e = (int)(nd / SEQ);
    float4 v = in[i];
    __half2 a = __floats2half2_rn(v.x, v.y);
    __half2 b = __floats2half2_rn(v.z, v.w);
    int mt = n >> 7, r = n & 127, kt = d >> 6, c = d & 63;
    size_t tile = ((size_t)(e * (SEQ / 128) + mt) * (DIM / 64) + kt) << 14;
    char* p = (char*)g_xT + tile + (size_t)r * 128
            + ((((c >> 3) ^ (r & 7)) << 4) + (c & 7) * 2);
    uint2 o;
    o.x = *reinterpret_cast<uint32_t*>(&a);
    o.y = *reinterpret_cast<uint32_t*>(&b);
    *reinterpret_cast<uint2*>(p) = o;
}

// w [e][k][nd] -> B-tiles [e][kt][nt][64x128 swizzled]
__global__ void cvt_w_tiled(const float4* __restrict__ in, __half* __restrict__ out,
                            int Kd, int Nd) {
    size_t i = (size_t)blockIdx.x * blockDim.x + threadIdx.x;  // E*Kd*Nd/4
    size_t base = i * 4;
    int n = (int)(base % Nd);
    size_t kn = base / Nd;
    int k = (int)(kn % Kd);
    int e = (int)(kn / Kd);
    float4 v = in[i];
    __half2 a = __floats2half2_rn(v.x, v.y);
    __half2 b = __floats2half2_rn(v.z, v.w);
    int kt = k >> 6, r = k & 63, nt = n >> 7, c = n & 127;
    size_t tile = ((size_t)(e * (Kd >> 6) + kt) * (Nd >> 7) + nt) << 14;
    char* p = (char*)out + tile + (size_t)r * 256 + ((c >> 6) << 7)
            + (((((c >> 3) & 7) ^ (r & 7)) << 4) + (c & 7) * 2);
    uint2 o;
    o.x = *reinterpret_cast<uint32_t*>(&a);
    o.y = *reinterpret_cast<uint32_t*>(&b);
    *reinterpret_cast<uint2*>(p) = o;
}

// ---------------- launch ----------------
extern "C" void kernel_launch(void* const* d_in, const int* in_sizes, int n_in,
                              void* d_out, int out_size) {
    const float* x  = (const float*)d_in[0];
    const float* w1 = (const float*)d_in[1];
    const float* w2 = (const float*)d_in[2];
    float* out = (float*)d_out;

    __half *pxT, *pw1T, *pw2T, *phT;
    cudaGetSymbolAddress((void**)&pxT,  g_xT);
    cudaGetSymbolAddress((void**)&pw1T, g_w1T);
    cudaGetSymbolAddress((void**)&pw2T, g_w2T);
    cudaGetSymbolAddress((void**)&phT,  g_hT);

    cudaFuncSetAttribute(gemm_bulk<1>, cudaFuncAttributeMaxDynamicSharedMemorySize, SMEM_TOTAL);
    cudaFuncSetAttribute(gemm_bulk<0>, cudaFuncAttributeMaxDynamicSharedMemorySize, SMEM_TOTAL);

    const size_t nx = (size_t)EXPERTS * SEQ * DIM;   // 33.5M
    const size_t nw = (size_t)EXPERTS * DIM * HID;   // 67.1M
    cvt_x_tiled<<<(unsigned)(nx / 4 / 256), 256>>>((const float4*)x);
    cvt_w_tiled<<<(unsigned)(nw / 4 / 256), 256>>>((const float4*)w1, pw1T, DIM, HID);
    cvt_w_tiled<<<(unsigned)(nw / 4 / 256), 256>>>((const float4*)w2, pw2T, HID, DIM);

    // GEMM1: hT = gelu(x @ w1)  M=SEQ,N=HID,K=DIM; KT=16, NT=32
    gemm_bulk<1><<<dim3(HID / BN, SEQ / BM, EXPERTS), NTHR, SMEM_TOTAL>>>(
        pxT, pw1T, phT, DIM / 64, HID / 128, 0, 0);

    // GEMM2: out = hid @ w2     M=SEQ,N=DIM,K=HID; KT=64, NT=8
    gemm_bulk<0><<<dim3(DIM / BN, SEQ / BM, EXPERTS), NTHR, SMEM_TOTAL>>>(
        phT, pw2T, out, HID / 64, DIM / 128, DIM, (size_t)SEQ * DIM);
}

// round 9
// speedup vs baseline: 1.1768x; 1.0654x over previous
#include <cuda_runtime.h>
#include <cuda_fp16.h>
#include <cstdint>

#define EXPERTS 16
#define SEQ     2048
#define DIM     1024
#define HID     4096

// Tiled+swizzled fp16 scratch. A-tile = 128x64 (16KB), B-tile = 64x128 (16KB),
// stored exactly in the smem image so the mainloop does contiguous 16KB bulk copies.
__device__ __half g_xT [(size_t)EXPERTS * SEQ * DIM];   // x   A-tiles [e][mt][kt]
__device__ __half g_w1T[(size_t)EXPERTS * DIM * HID];   // w1  B-tiles [e][kt][nt]
__device__ __half g_w2T[(size_t)EXPERTS * HID * DIM];   // w2  B-tiles [e][kt][nt]
__device__ __half g_hT [(size_t)EXPERTS * SEQ * HID];   // gelu(x@w1) A-tiles [e][mt][kt]

// ---------------- PTX helpers (base sm_103-safe) ----------------
static __device__ __forceinline__ uint32_t smem_u32(const void* p) {
    return (uint32_t)__cvta_generic_to_shared(p);
}
static __device__ __forceinline__ void mbar_init(uint32_t a, uint32_t cnt) {
    asm volatile("mbarrier.init.shared.b64 [%0], %1;" :: "r"(a), "r"(cnt) : "memory");
}
static __device__ __forceinline__ void mbar_expect(uint32_t a, uint32_t bytes) {
    asm volatile("mbarrier.arrive.expect_tx.shared.b64 _, [%0], %1;"
                 :: "r"(a), "r"(bytes) : "memory");
}
static __device__ __forceinline__ void mbar_arrive(uint32_t a) {
    asm volatile("mbarrier.arrive.shared.b64 _, [%0];" :: "r"(a) : "memory");
}
static __device__ __forceinline__ void bulk_g2s(uint32_t dst, const void* src,
                                                uint32_t bytes, uint32_t mbar) {
    asm volatile(
        "cp.async.bulk.shared::cluster.global.mbarrier::complete_tx::bytes "
        "[%0], [%1], %2, [%3];"
        :: "r"(dst), "l"(src), "r"(bytes), "r"(mbar) : "memory");
}
static __device__ __forceinline__ void mbar_wait(uint32_t a, uint32_t parity) {
    asm volatile(
        "{\n\t.reg .pred P;\n\t"
        "WL%=:\n\t"
        "mbarrier.try_wait.parity.acquire.cta.shared::cta.b64 P, [%0], %1, 0x989680;\n\t"
        "@!P bra WL%=;\n\t}"
        :: "r"(a), "r"(parity) : "memory");
}
static __device__ __forceinline__ void ldsm_x4(uint32_t* r, uint32_t a) {
    asm volatile("ldmatrix.sync.aligned.m8n8.x4.shared.b16 {%0,%1,%2,%3}, [%4];"
                 : "=r"(r[0]), "=r"(r[1]), "=r"(r[2]), "=r"(r[3]) : "r"(a));
}
static __device__ __forceinline__ void ldsm_x4_t(uint32_t* r, uint32_t a) {
    asm volatile("ldmatrix.sync.aligned.m8n8.x4.trans.shared.b16 {%0,%1,%2,%3}, [%4];"
                 : "=r"(r[0]), "=r"(r[1]), "=r"(r[2]), "=r"(r[3]) : "r"(a));
}
static __device__ __forceinline__ void mma16816(float* d, const uint32_t* a,
                                                uint32_t b0, uint32_t b1) {
    asm volatile(
        "mma.sync.aligned.m16n8k16.row.col.f32.f16.f16.f32 "
        "{%0,%1,%2,%3}, {%4,%5,%6,%7}, {%8,%9}, {%0,%1,%2,%3};"
        : "+f"(d[0]), "+f"(d[1]), "+f"(d[2]), "+f"(d[3])
        : "r"(a[0]), "r"(a[1]), "r"(a[2]), "r"(a[3]), "r"(b0), "r"(b1));
}
static __device__ __forceinline__ float gelu_f(float v) {
    return 0.5f * v * (1.0f + erff(v * 0.70710678118654752f));
}

// -------- GEMM: C[128x128] = A-tiles x B-tiles; 2 CTAs/SM; no __syncthreads --------
constexpr int BM = 128, BN = 128, BK = 64, STAGES = 3, NTHR = 256;
constexpr int TILE_B = 16384;                        // bytes per tile
constexpr int ST_B   = 2 * TILE_B;                   // A+B per stage
constexpr int OFF_T  = 1024;                         // barriers below
constexpr int SMEM_TOTAL = OFF_T + STAGES * ST_B;    // 99328 -> 2 CTA/SM
// smem ctrl: full[s] at sb+8*s (count 1), empty[s] at sb+64+8*s (count 8 warps)

template <int GELU_OUT>
__global__ void __launch_bounds__(NTHR, 2)
gemm_bulk(const __half* __restrict__ Atiles, const __half* __restrict__ Btiles,
          void* __restrict__ C0, int KT, int NT, int ldc, size_t sC)
{
    extern __shared__ char smem[];
    const uint32_t sb = smem_u32(smem);
    const int tid = threadIdx.x;
    const int e = blockIdx.z, by = blockIdx.y, bx = blockIdx.x;

    const char* Abase = (const char*)Atiles + ((size_t)(e * gridDim.y + by) * KT) * TILE_B;
    const char* Bbase = (const char*)Btiles + ((size_t)e * KT * NT + bx) * TILE_B;
    const size_t bstep = (size_t)NT * TILE_B;

    if (tid == 0) {
#pragma unroll
        for (int s = 0; s < STAGES; s++) {
            mbar_init(sb + 8 * s, 1);        // full
            mbar_init(sb + 64 + 8 * s, 8);   // empty: one arrive per warp
        }
    }
    __syncthreads();                         // barrier-init visibility (only sync)

    const int wid = tid >> 5, lid = tid & 31;
    const int wm = wid & 3, wn = wid >> 2;   // 4(M) x 2(N), warp tile 32x64
    const int sub = lid >> 3, rr = lid & 7;
    const int rowA0 = wm * 32 + rr + ((sub & 1) << 3);
    const int krow0 = rr + ((sub & 1) << 3);
    const int nch0  = (wn * 64 + ((sub >> 1) << 3)) >> 3;

    float acc[2][8][4];
#pragma unroll
    for (int mt = 0; mt < 2; mt++)
#pragma unroll
        for (int nt = 0; nt < 8; nt++)
#pragma unroll
            for (int q = 0; q < 4; q++) acc[mt][nt][q] = 0.f;

    // producer prologue: fill slots 0..STAGES-2
    if (tid == 0) {
#pragma unroll
        for (int it = 0; it < STAGES - 1; it++) {
            uint32_t mb = sb + 8 * it, da = sb + OFF_T + it * ST_B;
            mbar_expect(mb, ST_B);
            bulk_g2s(da,          Abase + (size_t)it * TILE_B, TILE_B, mb);
            bulk_g2s(da + TILE_B, Bbase + (size_t)it * bstep,  TILE_B, mb);
        }
    }

    for (int i = 0; i < KT; i++) {
        const int s = i % STAGES;
        mbar_wait(sb + 8 * s, (i / STAGES) & 1);
        // entering slab i => this warp is done reading slot (i-1)%STAGES
        if (i >= 1 && lid == 0) mbar_arrive(sb + 64 + 8 * ((i - 1) % STAGES));
        // producer refills slot (i+2)%STAGES for iteration nx=i+2
        if (tid == 0) {
            int nx = i + STAGES - 1;
            if (nx < KT) {
                int s2 = nx % STAGES;
                if (nx >= STAGES)            // wait all warps done with old contents
                    mbar_wait(sb + 64 + 8 * s2, ((nx - STAGES) / STAGES) & 1);
                uint32_t mb = sb + 8 * s2, da = sb + OFF_T + s2 * ST_B;
                mbar_expect(mb, ST_B);
                bulk_g2s(da,          Abase + (size_t)nx * TILE_B, TILE_B, mb);
                bulk_g2s(da + TILE_B, Bbase + (size_t)nx * bstep,  TILE_B, mb);
            }
        }

        const uint32_t sa  = sb + OFF_T + s * ST_B;
        const uint32_t sbb = sa + TILE_B;
#pragma unroll
        for (int kk = 0; kk < 4; kk++) {
            uint32_t af[2][4];
#pragma unroll
            for (int mt = 0; mt < 2; mt++) {
                int row = rowA0 + mt * 16;
                int ch = 2 * kk + (sub >> 1);
                ldsm_x4(af[mt], sa + row * 128 + ((ch ^ (row & 7)) << 4));
            }
            uint32_t bf[4][4];
#pragma unroll
            for (int nt2 = 0; nt2 < 4; nt2++) {
                int krow = kk * 16 + krow0;
                int cw = nch0 + nt2 * 2;
                ldsm_x4_t(bf[nt2], sbb + krow * 256 + ((cw >> 3) << 7) +
                                   (((cw & 7) ^ (krow & 7)) << 4));
            }
#pragma unroll
            for (int mt = 0; mt < 2; mt++)
#pragma unroll
                for (int nt2 = 0; nt2 < 4; nt2++) {
                    mma16816(acc[mt][nt2 * 2],     af[mt], bf[nt2][0], bf[nt2][1]);
                    mma16816(acc[mt][nt2 * 2 + 1], af[mt], bf[nt2][2], bf[nt2][3]);
                }
        }
    }

    // Epilogue. C frag m16n8: lane -> rows r0, r0+8 ; cols cq, cq+1.
    const int r0 = lid >> 2, cq = (lid & 3) * 2;
    if (GELU_OUT) {
        // write g_hT as GEMM2 A-tiles: tile (e, mt=by, ktg = bx*2 + (cl>>6))
        char* Hb = (char*)C0 + ((size_t)(e * (SEQ / 128) + by) * (HID / 64) + bx * 2) * TILE_B;
#pragma unroll
        for (int mt = 0; mt < 2; mt++) {
            int r1 = wm * 32 + mt * 16 + r0;          // r1&7 == r0
#pragma unroll
            for (int nt = 0; nt < 8; nt++) {
                int cl = wn * 64 + nt * 8 + cq;
                int cc = cl & 63;
                float* q = acc[mt][nt];
                __half2 h0 = __floats2half2_rn(gelu_f(q[0]), gelu_f(q[1]));
                __half2 h1 = __floats2half2_rn(gelu_f(q[2]), gelu_f(q[3]));
                char* p = Hb + ((size_t)(cl >> 6) << 14)
                             + ((((cc >> 3) ^ (r0 & 7)) << 4) + (cc & 7) * 2);
                *reinterpret_cast<__half2*>(p + (size_t)r1 * 128) = h0;
                *reinterpret_cast<__half2*>(p + (size_t)(r1 + 8) * 128) = h1;
            }
        }
    } else {
        const int m0 = by * BM, n0 = bx * BN;
#pragma unroll
        for (int mt = 0; mt < 2; mt++) {
            int rbase = m0 + wm * 32 + mt * 16 + r0;
#pragma unroll
            for (int nt = 0; nt < 8; nt++) {
                int col = n0 + wn * 64 + nt * 8 + cq;
                float* q = acc[mt][nt];
                float* C = (float*)C0 + e * sC + (size_t)rbase * ldc + col;
                *reinterpret_cast<float2*>(C) = make_float2(q[0], q[1]);
                *reinterpret_cast<float2*>(C + (size_t)8 * ldc) = make_float2(q[2], q[3]);
            }
        }
    }
}

// ---------------- conversion: fp32 -> fp16 tiled+swizzled ----------------
// x [e][n][d] -> A-tiles [e][mt][kt][128x64 swizzled]
__global__ void cvt_x_tiled(const float4* __restrict__ in) {
    size_t i = (size_t)blockIdx.x * blockDim.x + threadIdx.x;  // E*SEQ*DIM/4
    size_t base = i * 4;
    int d = (int)(base % DIM);
    size_t nd = base / DIM;
    int n = (int)(nd % SEQ);
    int e = (int)(nd / SEQ);
    float4 v = in[i];
    __half2 a = __floats2half2_rn(v.x, v.y);
    __half2 b = __floats2half2_rn(v.z, v.w);
    int mt = n >> 7, r = n & 127, kt = d >> 6, c = d & 63;
    size_t tile = ((size_t)(e * (SEQ / 128) + mt) * (DIM / 64) + kt) << 14;
    char* p = (char*)g_xT + tile + (size_t)r * 128
            + ((((c >> 3) ^ (r & 7)) << 4) + (c & 7) * 2);
    uint2 o;
    o.x = *reinterpret_cast<uint32_t*>(&a);
    o.y = *reinterpret_cast<uint32_t*>(&b);
    *reinterpret_cast<uint2*>(p) = o;
}

// w [e][k][nd] -> B-tiles [e][kt][nt][64x128 swizzled]
__global__ void cvt_w_tiled(const float4* __restrict__ in, __half* __restrict__ out,
                            int Kd, int Nd) {
    size_t i = (size_t)blockIdx.x * blockDim.x + threadIdx.x;  // E*Kd*Nd/4
    size_t base = i * 4;
    int n = (int)(base % Nd);
    size_t kn = base / Nd;
    int k = (int)(kn % Kd);
    int e = (int)(kn / Kd);
    float4 v = in[i];
    __half2 a = __floats2half2_rn(v.x, v.y);
    __half2 b = __floats2half2_rn(v.z, v.w);
    int kt = k >> 6, r = k & 63, nt = n >> 7, c = n & 127;
    size_t tile = ((size_t)(e * (Kd >> 6) + kt) * (Nd >> 7) + nt) << 14;
    char* p = (char*)out + tile + (size_t)r * 256 + ((c >> 6) << 7)
            + (((((c >> 3) & 7) ^ (r & 7)) << 4) + (c & 7) * 2);
    uint2 o;
    o.x = *reinterpret_cast<uint32_t*>(&a);
    o.y = *reinterpret_cast<uint32_t*>(&b);
    *reinterpret_cast<uint2*>(p) = o;
}

// ---------------- launch ----------------
extern "C" void kernel_launch(void* const* d_in, const int* in_sizes, int n_in,
                              void* d_out, int out_size) {
    const float* x  = (const float*)d_in[0];
    const float* w1 = (const float*)d_in[1];
    const float* w2 = (const float*)d_in[2];
    float* out = (float*)d_out;

    __half *pxT, *pw1T, *pw2T, *phT;
    cudaGetSymbolAddress((void**)&pxT,  g_xT);
    cudaGetSymbolAddress((void**)&pw1T, g_w1T);
    cudaGetSymbolAddress((void**)&pw2T, g_w2T);
    cudaGetSymbolAddress((void**)&phT,  g_hT);

    cudaFuncSetAttribute(gemm_bulk<1>, cudaFuncAttributeMaxDynamicSharedMemorySize, SMEM_TOTAL);
    cudaFuncSetAttribute(gemm_bulk<0>, cudaFuncAttributeMaxDynamicSharedMemorySize, SMEM_TOTAL);

    const size_t nx = (size_t)EXPERTS * SEQ * DIM;   // 33.5M
    const size_t nw = (size_t)EXPERTS * DIM * HID;   // 67.1M
    cvt_x_tiled<<<(unsigned)(nx / 4 / 256), 256>>>((const float4*)x);
    cvt_w_tiled<<<(unsigned)(nw / 4 / 256), 256>>>((const float4*)w1, pw1T, DIM, HID);
    cvt_w_tiled<<<(unsigned)(nw / 4 / 256), 256>>>((const float4*)w2, pw2T, HID, DIM);

    // GEMM1: hT = gelu(x @ w1)  M=SEQ,N=HID,K=DIM; KT=16, NT=32
    gemm_bulk<1><<<dim3(HID / BN, SEQ / BM, EXPERTS), NTHR, SMEM_TOTAL>>>(
        pxT, pw1T, phT, DIM / 64, HID / 128, 0, 0);

    // GEMM2: out = hid @ w2     M=SEQ,N=DIM,K=HID; KT=64, NT=8
    gemm_bulk<0><<<dim3(DIM / BN, SEQ / BM, EXPERTS), NTHR, SMEM_TOTAL>>>(
        phT, pw2T, out, HID / 64, DIM / 128, DIM, (size_t)SEQ * DIM);
}

// round 11
// speedup vs baseline: 1.2032x; 1.0225x over previous
#include <cuda_runtime.h>
#include <cuda_fp16.h>
#include <cstdint>

#define EXPERTS 16
#define SEQ     2048
#define DIM     1024
#define HID     4096

// Tiled+swizzled fp16 scratch. A-tile = 128x64 (16KB), B-tile = 64x128 (16KB),
// stored exactly in the smem image so the mainloop does contiguous 16KB bulk copies.
__device__ __half g_xT [(size_t)EXPERTS * SEQ * DIM];   // x   A-tiles [e][mt][kt]
__device__ __half g_w1T[(size_t)EXPERTS * DIM * HID];   // w1  B-tiles [e][kt][nt]
__device__ __half g_w2T[(size_t)EXPERTS * HID * DIM];   // w2  B-tiles [e][kt][nt]
__device__ __half g_hT [(size_t)EXPERTS * SEQ * HID];   // gelu(x@w1) A-tiles [e][mt][kt]

// ---------------- PTX helpers (base sm_103-safe) ----------------
static __device__ __forceinline__ uint32_t smem_u32(const void* p) {
    return (uint32_t)__cvta_generic_to_shared(p);
}
static __device__ __forceinline__ void mbar_init(uint32_t a, uint32_t cnt) {
    asm volatile("mbarrier.init.shared.b64 [%0], %1;" :: "r"(a), "r"(cnt) : "memory");
}
static __device__ __forceinline__ void mbar_expect(uint32_t a, uint32_t bytes) {
    asm volatile("mbarrier.arrive.expect_tx.shared.b64 _, [%0], %1;"
                 :: "r"(a), "r"(bytes) : "memory");
}
static __device__ __forceinline__ void mbar_arrive(uint32_t a) {
    asm volatile("mbarrier.arrive.shared.b64 _, [%0];" :: "r"(a) : "memory");
}
static __device__ __forceinline__ void bulk_g2s(uint32_t dst, const void* src,
                                                uint32_t bytes, uint32_t mbar) {
    asm volatile(
        "cp.async.bulk.shared::cluster.global.mbarrier::complete_tx::bytes "
        "[%0], [%1], %2, [%3];"
        :: "r"(dst), "l"(src), "r"(bytes), "r"(mbar) : "memory");
}
static __device__ __forceinline__ void mbar_wait(uint32_t a, uint32_t parity) {
    asm volatile(
        "{\n\t.reg .pred P;\n\t"
        "WL%=:\n\t"
        "mbarrier.try_wait.parity.acquire.cta.shared::cta.b64 P, [%0], %1, 0x989680;\n\t"
        "@!P bra WL%=;\n\t}"
        :: "r"(a), "r"(parity) : "memory");
}
static __device__ __forceinline__ void ldsm_x4(uint32_t* r, uint32_t a) {
    asm volatile("ldmatrix.sync.aligned.m8n8.x4.shared.b16 {%0,%1,%2,%3}, [%4];"
                 : "=r"(r[0]), "=r"(r[1]), "=r"(r[2]), "=r"(r[3]) : "r"(a));
}
static __device__ __forceinline__ void ldsm_x4_t(uint32_t* r, uint32_t a) {
    asm volatile("ldmatrix.sync.aligned.m8n8.x4.trans.shared.b16 {%0,%1,%2,%3}, [%4];"
                 : "=r"(r[0]), "=r"(r[1]), "=r"(r[2]), "=r"(r[3]) : "r"(a));
}
static __device__ __forceinline__ void mma16816(float* d, const uint32_t* a,
                                                uint32_t b0, uint32_t b1) {
    asm volatile(
        "mma.sync.aligned.m16n8k16.row.col.f32.f16.f16.f32 "
        "{%0,%1,%2,%3}, {%4,%5,%6,%7}, {%8,%9}, {%0,%1,%2,%3};"
        : "+f"(d[0]), "+f"(d[1]), "+f"(d[2]), "+f"(d[3])
        : "r"(a[0]), "r"(a[1]), "r"(a[2]), "r"(a[3]), "r"(b0), "r"(b1));
}
static __device__ __forceinline__ float gelu_f(float v) {
    return 0.5f * v * (1.0f + erff(v * 0.70710678118654752f));
}

// -------- GEMM: C[128x128]; 4 warps (2x2), warp tile 64x64; 2 CTAs/SM --------
constexpr int BM = 128, BN = 128, BK = 64, STAGES = 3, NTHR = 128;
constexpr int TILE_B = 16384;                        // bytes per tile
constexpr int ST_B   = 2 * TILE_B;                   // A+B per stage
constexpr int OFF_T  = 1024;                         // barriers below
constexpr int SMEM_TOTAL = OFF_T + STAGES * ST_B;    // 99328 -> 2 CTA/SM
// smem ctrl: full[s] at sb+8*s (count 1), empty[s] at sb+64+8*s (count 4 warps)

template <int GELU_OUT>
__global__ void __launch_bounds__(NTHR, 2)
gemm_bulk(const __half* __restrict__ Atiles, const __half* __restrict__ Btiles,
          void* __restrict__ C0, int KT, int NT, int ldc, size_t sC)
{
    extern __shared__ char smem[];
    const uint32_t sb = smem_u32(smem);
    const int tid = threadIdx.x;
    const int e = blockIdx.z, by = blockIdx.y, bx = blockIdx.x;

    const char* Abase = (const char*)Atiles + ((size_t)(e * gridDim.y + by) * KT) * TILE_B;
    const char* Bbase = (const char*)Btiles + ((size_t)e * KT * NT + bx) * TILE_B;
    const size_t bstep = (size_t)NT * TILE_B;

    if (tid == 0) {
#pragma unroll
        for (int s = 0; s < STAGES; s++) {
            mbar_init(sb + 8 * s, 1);        // full
            mbar_init(sb + 64 + 8 * s, 4);   // empty: one arrive per warp
        }
    }
    __syncthreads();                         // barrier-init visibility (only sync)

    const int wid = tid >> 5, lid = tid & 31;
    const int wm = wid & 1, wn = wid >> 1;   // 2(M) x 2(N), warp tile 64x64
    const int sub = lid >> 3, rr = lid & 7;
    const int rowA0 = wm * 64 + rr + ((sub & 1) << 3);   // + mt*16
    const int krow0 = rr + ((sub & 1) << 3);             // + kk*16
    const int nch0  = wn * 8 + (sub >> 1);               // 16B-chunk of 16/row, + nt2*2

    float acc[4][8][4];
#pragma unroll
    for (int mt = 0; mt < 4; mt++)
#pragma unroll
        for (int nt = 0; nt < 8; nt++)
#pragma unroll
            for (int q = 0; q < 4; q++) acc[mt][nt][q] = 0.f;

    // producer prologue: fill slots 0..STAGES-2
    if (tid == 0) {
#pragma unroll
        for (int it = 0; it < STAGES - 1; it++) {
            uint32_t mb = sb + 8 * it, da = sb + OFF_T + it * ST_B;
            mbar_expect(mb, ST_B);
            bulk_g2s(da,          Abase + (size_t)it * TILE_B, TILE_B, mb);
            bulk_g2s(da + TILE_B, Bbase + (size_t)it * bstep,  TILE_B, mb);
        }
    }

    for (int i = 0; i < KT; i++) {
        const int s = i % STAGES;
        mbar_wait(sb + 8 * s, (i / STAGES) & 1);
        // entering slab i => this warp is done reading slot (i-1)%STAGES
        if (i >= 1 && lid == 0) mbar_arrive(sb + 64 + 8 * ((i - 1) % STAGES));
        // producer refills slot for iteration nx = i+STAGES-1
        if (tid == 0) {
            int nx = i + STAGES - 1;
            if (nx < KT) {
                int s2 = nx % STAGES;
                if (nx >= STAGES)            // wait all warps done with old contents
                    mbar_wait(sb + 64 + 8 * s2, ((nx - STAGES) / STAGES) & 1);
                uint32_t mb = sb + 8 * s2, da = sb + OFF_T + s2 * ST_B;
                mbar_expect(mb, ST_B);
                bulk_g2s(da,          Abase + (size_t)nx * TILE_B, TILE_B, mb);
                bulk_g2s(da + TILE_B, Bbase + (size_t)nx * bstep,  TILE_B, mb);
            }
        }

        const uint32_t sa  = sb + OFF_T + s * ST_B;
        const uint32_t sbb = sa + TILE_B;
#pragma unroll
        for (int kk = 0; kk < 4; kk++) {
            // B fragments: 4 x ldsm.x4.t covering 64 cols x k16
            uint32_t bf[4][4];
#pragma unroll
            for (int nt2 = 0; nt2 < 4; nt2++) {
                int krow = kk * 16 + krow0;
                int cw = nch0 + nt2 * 2;
                ldsm_x4_t(bf[nt2], sbb + krow * 256 + ((cw >> 3) << 7) +
                                   (((cw & 7) ^ (krow & 7)) << 4));
            }
            // A fragments: 4 x ldsm.x4 covering 64 rows x k16; 32 MMAs
#pragma unroll
            for (int mt = 0; mt < 4; mt++) {
                uint32_t af[4];
                int row = rowA0 + mt * 16;
                int ch = 2 * kk + (sub >> 1);
                ldsm_x4(af, sa + row * 128 + ((ch ^ (row & 7)) << 4));
#pragma unroll
                for (int nt2 = 0; nt2 < 4; nt2++) {
                    mma16816(acc[mt][nt2 * 2],     af, bf[nt2][0], bf[nt2][1]);
                    mma16816(acc[mt][nt2 * 2 + 1], af, bf[nt2][2], bf[nt2][3]);
                }
            }
        }
    }

    // Epilogue. C frag m16n8: lane -> rows r0, r0+8 ; cols cq, cq+1.
    const int r0 = lid >> 2, cq = (lid & 3) * 2;
    if (GELU_OUT) {
        // write g_hT as GEMM2 A-tiles: tile (e, mt=by, ktg = bx*2 + (cl>>6))
        char* Hb = (char*)C0 + ((size_t)(e * (SEQ / 128) + by) * (HID / 64) + bx * 2) * TILE_B;
#pragma unroll
        for (int mt = 0; mt < 4; mt++) {
            int r1 = wm * 64 + mt * 16 + r0;          // r1&7 == r0&7
#pragma unroll
            for (int nt = 0; nt < 8; nt++) {
                int cl = wn * 64 + nt * 8 + cq;
                int cc = cl & 63;
                float* q = acc[mt][nt];
                __half2 h0 = __floats2half2_rn(gelu_f(q[0]), gelu_f(q[1]));
                __half2 h1 = __floats2half2_rn(gelu_f(q[2]), gelu_f(q[3]));
                char* p = Hb + ((size_t)(cl >> 6) << 14)
                             + ((((cc >> 3) ^ (r0 & 7)) << 4) + (cc & 7) * 2);
                *reinterpret_cast<__half2*>(p + (size_t)r1 * 128) = h0;
                *reinterpret_cast<__half2*>(p + (size_t)(r1 + 8) * 128) = h1;
            }
        }
    } else {
        const int m0 = by * BM, n0 = bx * BN;
#pragma unroll
        for (int mt = 0; mt < 4; mt++) {
            int rbase = m0 + wm * 64 + mt * 16 + r0;
#pragma unroll
            for (int nt = 0; nt < 8; nt++) {
                int col = n0 + wn * 64 + nt * 8 + cq;
                float* q = acc[mt][nt];
                float* C = (float*)C0 + e * sC + (size_t)rbase * ldc + col;
                *reinterpret_cast<float2*>(C) = make_float2(q[0], q[1]);
                *reinterpret_cast<float2*>(C + (size_t)8 * ldc) = make_float2(q[2], q[3]);
            }
        }
    }
}

// ---------------- conversion: fp32 -> fp16 tiled+swizzled ----------------
// x [e][n][d] -> A-tiles [e][mt][kt][128x64 swizzled]
__global__ void cvt_x_tiled(const float4* __restrict__ in) {
    size_t i = (size_t)blockIdx.x * blockDim.x + threadIdx.x;  // E*SEQ*DIM/4
    size_t base = i * 4;
    int d = (int)(base % DIM);
    size_t nd = base / DIM;
    int n = (int)(nd % SEQ);
    int e = (int)(nd / SEQ);
    float4 v = in[i];
    __half2 a = __floats2half2_rn(v.x, v.y);
    __half2 b = __floats2half2_rn(v.z, v.w);
    int mt = n >> 7, r = n & 127, kt = d >> 6, c = d & 63;
    size_t tile = ((size_t)(e * (SEQ / 128) + mt) * (DIM / 64) + kt) << 14;
    char* p = (char*)g_xT + tile + (size_t)r * 128
            + ((((c >> 3) ^ (r & 7)) << 4) + (c & 7) * 2);
    uint2 o;
    o.x = *reinterpret_cast<uint32_t*>(&a);
    o.y = *reinterpret_cast<uint32_t*>(&b);
    *reinterpret_cast<uint2*>(p) = o;
}

// w [e][k][nd] -> B-tiles [e][kt][nt][64x128 swizzled]
__global__ void cvt_w_tiled(const float4* __restrict__ in, __half* __restrict__ out,
                            int Kd, int Nd) {
    size_t i = (size_t)blockIdx.x * blockDim.x + threadIdx.x;  // E*Kd*Nd/4
    size_t base = i * 4;
    int n = (int)(base % Nd);
    size_t kn = base / Nd;
    int k = (int)(kn % Kd);
    int e = (int)(kn / Kd);
    float4 v = in[i];
    __half2 a = __floats2half2_rn(v.x, v.y);
    __half2 b = __floats2half2_rn(v.z, v.w);
    int kt = k >> 6, r = k & 63, nt = n >> 7, c = n & 127;
    size_t tile = ((size_t)(e * (Kd >> 6) + kt) * (Nd >> 7) + nt) << 14;
    char* p = (char*)out + tile + (size_t)r * 256 + ((c >> 6) << 7)
            + (((((c >> 3) & 7) ^ (r & 7)) << 4) + (c & 7) * 2);
    uint2 o;
    o.x = *reinterpret_cast<uint32_t*>(&a);
    o.y = *reinterpret_cast<uint32_t*>(&b);
    *reinterpret_cast<uint2*>(p) = o;
}

// ---------------- launch ----------------
extern "C" void kernel_launch(void* const* d_in, const int* in_sizes, int n_in,
                              void* d_out, int out_size) {
    const float* x  = (const float*)d_in[0];
    const float* w1 = (const float*)d_in[1];
    const float* w2 = (const float*)d_in[2];
    float* out = (float*)d_out;

    __half *pxT, *pw1T, *pw2T, *phT;
    cudaGetSymbolAddress((void**)&pxT,  g_xT);
    cudaGetSymbolAddress((void**)&pw1T, g_w1T);
    cudaGetSymbolAddress((void**)&pw2T, g_w2T);
    cudaGetSymbolAddress((void**)&phT,  g_hT);

    cudaFuncSetAttribute(gemm_bulk<1>, cudaFuncAttributeMaxDynamicSharedMemorySize, SMEM_TOTAL);
    cudaFuncSetAttribute(gemm_bulk<0>, cudaFuncAttributeMaxDynamicSharedMemorySize, SMEM_TOTAL);

    const size_t nx = (size_t)EXPERTS * SEQ * DIM;   // 33.5M
    const size_t nw = (size_t)EXPERTS * DIM * HID;   // 67.1M
    cvt_x_tiled<<<(unsigned)(nx / 4 / 256), 256>>>((const float4*)x);
    cvt_w_tiled<<<(unsigned)(nw / 4 / 256), 256>>>((const float4*)w1, pw1T, DIM, HID);
    cvt_w_tiled<<<(unsigned)(nw / 4 / 256), 256>>>((const float4*)w2, pw2T, HID, DIM);

    // GEMM1: hT = gelu(x @ w1)  M=SEQ,N=HID,K=DIM; KT=16, NT=32
    gemm_bulk<1><<<dim3(HID / BN, SEQ / BM, EXPERTS), NTHR, SMEM_TOTAL>>>(
        pxT, pw1T, phT, DIM / 64, HID / 128, 0, 0);

    // GEMM2: out = hid @ w2     M=SEQ,N=DIM,K=HID; KT=64, NT=8
    gemm_bulk<0><<<dim3(DIM / BN, SEQ / BM, EXPERTS), NTHR, SMEM_TOTAL>>>(
        phT, pw2T, out, HID / 64, DIM / 128, DIM, (size_t)SEQ * DIM);
}